// round 9
// baseline (speedup 1.0000x reference)
#include <cuda_runtime.h>
#include <cuda_bf16.h>
#include <cstdint>

// ===========================================================================
// SLAYER SNN forward. GEMM1 on int8 tensor cores (mma.m16n8k32.s8.s8.s32):
// spikes are exact in s8; W1 split into 3 s8 digits (bases 2^-10/2^-18/2^-26,
// residual <= 2^-27). s32 accumulation is EXACT; fp32 recombine in epilogue.
// ===========================================================================

#define BATCH 32
#define TBINS 300
#define FIN   3072
#define HID   410
#define NOUT  10
#define MROWS (BATCH * TBINS)          // 9600
#define NTOT  (MROWS * FIN)
#define HALFN (NTOT / 2)               // 14745600 = 4800*3072
#define NPAD  416                      // 13 tiles of 32

#define DECAY 0.90483743f
#define THETA 10.0f

// digit bases
#define B1F 9.765625e-4f               // 2^-10
#define B2F 3.814697265625e-6f         // 2^-18
#define B3F 1.4901161193847656e-8f     // 2^-26

// GEMM1 tiling
#define NPARTS 3
#define BM 128
#define BN 32
#define BK 64                          // int8 elems per k-chunk (64B rows, SW64)
#define KCH (FIN / BK)                 // 48
#define BROWS (NPARTS * BN)            // 96
#define A_ST_BYTES (BM * 64)           // 8192
#define B_ST_BYTES (BROWS * 64)        // 6144
#define STAGE_BYTES (A_ST_BYTES + B_ST_BYTES)   // 14336
#define NSTAGES 4
#define DSMEM_BYTES (NSTAGES * STAGE_BYTES)     // 57344
#define NCHUNK (STAGE_BYTES / 16)      // 896
#define ACHUNK (A_ST_BYTES / 16)       // 512

#define SWZ64(off) ((off) ^ (((off) >> 3) & 0x30))

// Scratch
__device__ __align__(16) int8_t        g_spikes[NTOT];              // 0/1
__device__ __align__(16) int8_t        g_W1q[NPARTS * NPAD * FIN];  // digit planes
__device__ __align__(16) float         g_a1[MROWS * HID];
__device__ __align__(16) __nv_bfloat16 g_s1[MROWS * HID];
__device__ __align__(16) float         g_a2[MROWS * NOUT];

// ---------------------------------------------------------------------------
__device__ __forceinline__ uint32_t smem_u32(const void* p) {
    uint32_t a;
    asm("{ .reg .u64 t; cvta.to.shared.u64 t, %1; cvt.u32.u64 %0, t; }" : "=r"(a) : "l"(p));
    return a;
}
__device__ __forceinline__ void cp16(uint32_t sa, const void* g) {
    asm volatile("cp.async.cg.shared.global [%0], [%1], 16;" :: "r"(sa), "l"(g));
}
__device__ __forceinline__ void ldsm4(uint32_t* r, uint32_t addr) {
    asm volatile("ldmatrix.sync.aligned.m8n8.x4.shared.b16 {%0,%1,%2,%3}, [%4];"
                 : "=r"(r[0]), "=r"(r[1]), "=r"(r[2]), "=r"(r[3]) : "r"(addr));
}
__device__ __forceinline__ void mma16832s8(int* c, const uint32_t* a,
                                           uint32_t b0, uint32_t b1) {
    asm volatile(
        "mma.sync.aligned.m16n8k32.row.col.s32.s8.s8.s32 "
        "{%0,%1,%2,%3}, {%4,%5,%6,%7}, {%8,%9}, {%0,%1,%2,%3};"
        : "+r"(c[0]), "+r"(c[1]), "+r"(c[2]), "+r"(c[3])
        : "r"(a[0]), "r"(a[1]), "r"(a[2]), "r"(a[3]), "r"(b0), "r"(b1));
}

// ---------------------------------------------------------------------------
// Kernel 1: threefry spike generation -> s8 0/1 (bit-exact vs jax), 8 pairs
// per thread; W1 3-digit split on the first HID*FIN/8 threads.
// ---------------------------------------------------------------------------
__device__ __forceinline__ uint32_t rotl32(uint32_t x, int r) {
    return (x << r) | (x >> (32 - r));
}
__device__ __forceinline__ void wdigits(float w, int8_t& d1, int8_t& d2, int8_t& d3) {
    float q1 = rintf(w * 1024.0f);
    q1 = fminf(fmaxf(q1, -127.f), 127.f);
    float r1 = fmaf(q1, -B1F, w);                 // exact
    float q2 = rintf(r1 * 262144.0f);
    q2 = fminf(fmaxf(q2, -127.f), 127.f);
    float r2 = fmaf(q2, -B2F, r1);                // exact
    float q3 = rintf(r2 * 67108864.0f);
    q3 = fminf(fmaxf(q3, -127.f), 127.f);
    d1 = (int8_t)(int)q1; d2 = (int8_t)(int)q2; d3 = (int8_t)(int)q3;
}

__global__ void __launch_bounds__(256) spikegen_kernel(const float* __restrict__ inp,
                                                       const float* __restrict__ W1) {
    const uint32_t t = blockIdx.x * 256u + threadIdx.x;

    // --- W1 digit split, 8 consecutive elements per thread ---
    if (t < (HID * FIN) / 8) {
        int base = t * 8;
        int n = base / FIN, k = base % FIN;
        float4 wa = *(const float4*)&W1[base];
        float4 wb = *(const float4*)&W1[base + 4];
        float w[8] = {wa.x, wa.y, wa.z, wa.w, wb.x, wb.y, wb.z, wb.w};
        int8_t d1[8], d2[8], d3[8];
#pragma unroll
        for (int q = 0; q < 8; q++) wdigits(w[q], d1[q], d2[q], d3[q]);
        *(uint2*)&g_W1q[(0 * NPAD + n) * FIN + k] = *(uint2*)d1;
        *(uint2*)&g_W1q[(1 * NPAD + n) * FIN + k] = *(uint2*)d2;
        *(uint2*)&g_W1q[(2 * NPAD + n) * FIN + k] = *(uint2*)d3;
    }

    const uint32_t i0 = t * 8;
    if (i0 >= HALFN) return;

    const uint32_t ba = i0 / (TBINS * FIN);
    const uint32_t fa = i0 % FIN;                 // same f for both halves; b and b+16
    float4 p0 = *(const float4*)&inp[ba * FIN + fa];
    float4 p1 = *(const float4*)&inp[ba * FIN + fa + 4];
    float4 q0 = *(const float4*)&inp[(ba + 16) * FIN + fa];
    float4 q1 = *(const float4*)&inp[(ba + 16) * FIN + fa + 4];
    float pa[8] = {p0.x, p0.y, p0.z, p0.w, p1.x, p1.y, p1.z, p1.w};
    float pb[8] = {q0.x, q0.y, q0.z, q0.w, q1.x, q1.y, q1.z, q1.w};

    const uint32_t k0 = 0u, k1 = 42u, k2 = 0x1BD11BDAu ^ k0 ^ k1;
    int8_t sa[8], sb[8];

#pragma unroll
    for (int j = 0; j < 8; j++) {
        uint32_t i = i0 + j;
        uint32_t x0 = i + k0;
        uint32_t x1 = (i + HALFN) + k1;
#define TF_RND(r) { x0 += x1; x1 = rotl32(x1, (r)) ^ x0; }
        TF_RND(13) TF_RND(15) TF_RND(26) TF_RND(6)
        x0 += k1; x1 += k2 + 1u;
        TF_RND(17) TF_RND(29) TF_RND(16) TF_RND(24)
        x0 += k2; x1 += k0 + 2u;
        TF_RND(13) TF_RND(15) TF_RND(26) TF_RND(6)
        x0 += k0; x1 += k1 + 3u;
        TF_RND(17) TF_RND(29) TF_RND(16) TF_RND(24)
        x0 += k1; x1 += k2 + 4u;
        TF_RND(13) TF_RND(15) TF_RND(26) TF_RND(6)
        x0 += k2; x1 += k0 + 5u;
#undef TF_RND
        float u0 = __uint_as_float((x0 >> 9) | 0x3F800000u) - 1.0f;
        float u1 = __uint_as_float((x1 >> 9) | 0x3F800000u) - 1.0f;
        sa[j] = (u0 < pa[j]) ? 1 : 0;
        sb[j] = (u1 < pb[j]) ? 1 : 0;
    }

    *(uint2*)&g_spikes[i0]         = *(uint2*)sa;
    *(uint2*)&g_spikes[i0 + HALFN] = *(uint2*)sb;
}

// ---------------------------------------------------------------------------
// Kernel 2: GEMM1 int8, 4-stage cp.async pipeline, SW64 smem.
// a1[m,n] = (G1*2^-10 + G2*2^-18 + G3*2^-26), Gi = spikes @ digit_i^T (s32).
// ---------------------------------------------------------------------------
__device__ __forceinline__ void load_stage(uint32_t sbase, int m0, int n0, int k0,
                                           int tid) {
    uint32_t stB = sbase + A_ST_BYTES;
#pragma unroll
    for (int c = tid; c < NCHUNK; c += 256) {
        uint32_t sa;
        const int8_t* g;
        if (c < ACHUNK) {                               // A: 512 chunks (128 rows x 4)
            int row = c >> 2, q = c & 3;
            sa = sbase + SWZ64(row * 64 + q * 16);
            g = &g_spikes[(size_t)(m0 + row) * FIN + k0 + q * 16];
        } else {                                        // B: 384 chunks (96 rows x 4)
            int cc = c - ACHUNK;
            int br = cc >> 2, q = cc & 3;               // br 0..95
            int part = br >> 5, nr = br & 31;
            sa = stB + SWZ64(br * 64 + q * 16);
            g = &g_W1q[((size_t)part * NPAD + n0 + nr) * FIN + k0 + q * 16];
        }
        cp16(sa, g);
    }
    asm volatile("cp.async.commit_group;" ::: "memory");
}

__global__ void __launch_bounds__(256, 2) gemm1_mma_kernel() {
    extern __shared__ char dsmem[];
    const int tid = threadIdx.x;
    const int lane = tid & 31, wid = tid >> 5;
    const int wm = wid & 3;          // 4 m-warps (32 rows each)
    const int wn = wid >> 2;         // 2 n-warps (16 cols each)
    const int m0 = blockIdx.x * BM;
    const int n0 = blockIdx.y * BN;

    const uint32_t sbase = smem_u32(dsmem);

    int acc[NPARTS][2][2][4];
#pragma unroll
    for (int p = 0; p < NPARTS; p++)
#pragma unroll
        for (int i = 0; i < 2; i++)
#pragma unroll
            for (int j = 0; j < 2; j++)
#pragma unroll
                for (int c = 0; c < 4; c++) acc[p][i][j][c] = 0;

    const int ltr = (lane & 7) + ((lane >> 3) & 1) * 8;   // row within 16
    const int lkb = (lane >> 4) * 16;                     // 16B half select

    load_stage(sbase + 0 * STAGE_BYTES, m0, n0, 0 * BK, tid);
    load_stage(sbase + 1 * STAGE_BYTES, m0, n0, 1 * BK, tid);
    load_stage(sbase + 2 * STAGE_BYTES, m0, n0, 2 * BK, tid);

    for (int kc = 0; kc < KCH; kc++) {
        const int rem = KCH - 1 - kc;
        if (rem >= 2)      asm volatile("cp.async.wait_group 2;" ::: "memory");
        else if (rem == 1) asm volatile("cp.async.wait_group 1;" ::: "memory");
        else               asm volatile("cp.async.wait_group 0;" ::: "memory");
        __syncthreads();

        if (kc + 3 < KCH)
            load_stage(sbase + ((kc + 3) & 3) * STAGE_BYTES, m0, n0, (kc + 3) * BK, tid);

        const uint32_t sA = sbase + (kc & 3) * STAGE_BYTES;
        const uint32_t sB = sA + A_ST_BYTES;

#pragma unroll
        for (int kt = 0; kt < 2; kt++) {                  // 2 x k32 per stage
            const int kb = kt * 32 + lkb;
            uint32_t aF[2][4];
#pragma unroll
            for (int im = 0; im < 2; im++) {
                int row = wm * 32 + im * 16 + ltr;
                ldsm4(aF[im], sA + SWZ64(row * 64 + kb));
            }
#pragma unroll
            for (int part = 0; part < NPARTS; part++) {
                uint32_t bF[4];
                {
                    int row = part * 32 + wn * 16 + ltr;  // 16 n-rows for this warp
                    ldsm4(bF, sB + SWZ64(row * 64 + kb));
                }
#pragma unroll
                for (int im = 0; im < 2; im++)
#pragma unroll
                    for (int jn = 0; jn < 2; jn++)
                        mma16832s8(acc[part][im][jn], aF[im], bF[jn], bF[jn + 2]);
            }
        }
    }

    // epilogue: combine digit planes in fp32
#pragma unroll
    for (int im = 0; im < 2; im++) {
        int m = m0 + wm * 32 + im * 16 + (lane >> 2);
#pragma unroll
        for (int jn = 0; jn < 2; jn++) {
            int n = n0 + wn * 16 + jn * 8 + (lane & 3) * 2;
            if (n < HID) {
                float v[4];
#pragma unroll
                for (int c = 0; c < 4; c++) {
                    v[c] = fmaf((float)acc[0][im][jn][c], B1F,
                           fmaf((float)acc[1][im][jn][c], B2F,
                                (float)acc[2][im][jn][c] * B3F));
                }
                *(float2*)&g_a1[(size_t)m * HID + n]       = make_float2(v[0], v[1]);
                *(float2*)&g_a1[(size_t)(m + 8) * HID + n] = make_float2(v[2], v[3]);
            }
        }
    }
}

// ---------------------------------------------------------------------------
// Kernel 3: PSP + threshold layer 1 -> bf16. Batch-10 prefetch.
// ---------------------------------------------------------------------------
__global__ void __launch_bounds__(256) psp1_kernel() {
    int tid = blockIdx.x * blockDim.x + threadIdx.x;
    if (tid >= BATCH * HID) return;
    int b = tid / HID;
    int o = tid % HID;
    const float* src = &g_a1[(size_t)b * TBINS * HID + o];
    __nv_bfloat16* dst = &g_s1[(size_t)b * TBINS * HID + o];
    float u = 0.0f;
    for (int tb = 0; tb < TBINS; tb += 10) {
        float x[10];
#pragma unroll
        for (int q = 0; q < 10; q++) x[q] = src[(tb + q) * HID];
#pragma unroll
        for (int q = 0; q < 10; q++) {
            u = fmaf(DECAY, u, x[q]);
            dst[(tb + q) * HID] = __float2bfloat16((u >= THETA) ? 1.0f : 0.0f);
        }
    }
}

// ---------------------------------------------------------------------------
// Kernel 4: GEMM2 (one warp per row, bf16x2 vectorized)
// ---------------------------------------------------------------------------
__global__ void __launch_bounds__(256) gemm2_kernel(const float* __restrict__ W2) {
    __shared__ float2 W2s[NOUT][(HID + 1) / 2 + 1];
    for (int idx = threadIdx.x; idx < NOUT * 206; idx += 256) {
        int j = idx / 206, kp = idx % 206;
        float w0 = (kp * 2 < HID) ? W2[j * HID + kp * 2] : 0.0f;
        float w1 = (kp * 2 + 1 < HID) ? W2[j * HID + kp * 2 + 1] : 0.0f;
        W2s[j][kp] = make_float2(w0, w1);
    }
    __syncthreads();

    int warp = threadIdx.x >> 5;
    int lane = threadIdx.x & 31;
    int m = blockIdx.x * 8 + warp;

    float p[NOUT];
#pragma unroll
    for (int j = 0; j < NOUT; j++) p[j] = 0.0f;

    for (int kp = lane; kp < 205; kp += 32) {
        __nv_bfloat162 sv = *(const __nv_bfloat162*)&g_s1[m * HID + kp * 2];
        float s0 = __bfloat162float(sv.x);
        float s1v = __bfloat162float(sv.y);
#pragma unroll
        for (int j = 0; j < NOUT; j++) {
            float2 w = W2s[j][kp];
            p[j] = fmaf(s0, w.x, fmaf(s1v, w.y, p[j]));
        }
    }

#pragma unroll
    for (int j = 0; j < NOUT; j++)
#pragma unroll
        for (int off = 16; off > 0; off >>= 1)
            p[j] += __shfl_down_sync(0xffffffffu, p[j], off);

    if (lane == 0) {
#pragma unroll
        for (int j = 0; j < NOUT; j++)
            g_a2[m * NOUT + j] = p[j];
    }
}

// ---------------------------------------------------------------------------
// Kernel 5: PSP + threshold layer 2 -> out[b, j, t]. Batch-10 prefetch.
// ---------------------------------------------------------------------------
__global__ void psp2_kernel(float* __restrict__ out) {
    int tid = blockIdx.x * blockDim.x + threadIdx.x;
    if (tid >= BATCH * NOUT) return;
    int b = tid / NOUT;
    int j = tid % NOUT;
    const float* src = &g_a2[(size_t)b * TBINS * NOUT + j];
    float* dst = &out[((size_t)b * NOUT + j) * TBINS];
    float u = 0.0f;
    for (int tb = 0; tb < TBINS; tb += 10) {
        float x[10];
#pragma unroll
        for (int q = 0; q < 10; q++) x[q] = src[(tb + q) * NOUT];
#pragma unroll
        for (int q = 0; q < 10; q++) {
            u = fmaf(DECAY, u, x[q]);
            dst[tb + q] = (u >= THETA) ? 1.0f : 0.0f;
        }
    }
}

// ---------------------------------------------------------------------------
extern "C" void kernel_launch(void* const* d_in, const int* in_sizes, int n_in,
                              void* d_out, int out_size) {
    const float* inp = (const float*)d_in[0];   // [32,3,32,32]
    const float* W1  = (const float*)d_in[1];   // [410,3072]
    const float* W2  = (const float*)d_in[2];   // [10,410]
    float* out = (float*)d_out;                 // [32,10,300]

    cudaFuncSetAttribute(gemm1_mma_kernel,
                         cudaFuncAttributeMaxDynamicSharedMemorySize, DSMEM_BYTES);

    spikegen_kernel<<<HALFN / 8 / 256, 256>>>(inp, W1);   // 7200 blocks

    dim3 g1(MROWS / BM, NPAD / BN);   // (75, 13)
    gemm1_mma_kernel<<<g1, 256, DSMEM_BYTES>>>();

    psp1_kernel<<<(BATCH * HID + 255) / 256, 256>>>();
    gemm2_kernel<<<MROWS / 8, 256>>>(W2);
    psp2_kernel<<<2, 160>>>(out);
}

// round 10
// speedup vs baseline: 1.5275x; 1.5275x over previous
#include <cuda_runtime.h>
#include <cuda_fp16.h>
#include <cuda_bf16.h>
#include <cstdint>

// ===========================================================================
// SLAYER SNN forward. GEMM1: mma.sync.m16n8k16 fp16, 2-part fp16 split of W1
// (hi + mid), both fp32 accumulators (fastest mma.sync variant on sm_103:
// f16-acc same rate, s8 ~4x slower -- measured R8/R9).
// 4-stage cp.async pipeline (BK=32, SW64). Vectorized 8-pair threefry spikegen.
// ===========================================================================

#define BATCH 32
#define TBINS 300
#define FIN   3072
#define HID   410
#define NOUT  10
#define MROWS (BATCH * TBINS)          // 9600
#define NTOT  (MROWS * FIN)
#define HALFN (NTOT / 2)               // 14745600 = 4800*3072
#define NPAD  448

#define DECAY 0.90483743f
#define THETA 10.0f

// GEMM1 tiling
#define NPARTS 2
#define BM 256
#define BN 64
#define BK 32
#define KCH (FIN / BK)                 // 96
#define BROWS (NPARTS * BN)            // 128
#define A_ST_BYTES (BM * 64)           // 16384
#define B_ST_BYTES (BROWS * 64)        // 8192
#define STAGE_BYTES (A_ST_BYTES + B_ST_BYTES)   // 24576
#define NSTAGES 4
#define DSMEM_BYTES (NSTAGES * STAGE_BYTES)     // 98304
#define NCHUNK (STAGE_BYTES / 16)      // 1536
#define ACHUNK (A_ST_BYTES / 16)       // 1024

#define SWZ64(off) ((off) ^ (((off) >> 3) & 0x30))

// Scratch
__device__ __align__(16) __half        g_spikes[NTOT];
__device__ __align__(16) __half        g_W1s[NPARTS * NPAD * FIN];
__device__ __align__(16) float         g_a1[MROWS * HID];
__device__ __align__(16) __nv_bfloat16 g_s1[MROWS * HID];
__device__ __align__(16) float         g_a2[MROWS * NOUT];

// ---------------------------------------------------------------------------
__device__ __forceinline__ uint32_t smem_u32(const void* p) {
    uint32_t a;
    asm("{ .reg .u64 t; cvta.to.shared.u64 t, %1; cvt.u32.u64 %0, t; }" : "=r"(a) : "l"(p));
    return a;
}
__device__ __forceinline__ void cp16(uint32_t sa, const void* g) {
    asm volatile("cp.async.cg.shared.global [%0], [%1], 16;" :: "r"(sa), "l"(g));
}
__device__ __forceinline__ void ldsm4(uint32_t* r, uint32_t addr) {
    asm volatile("ldmatrix.sync.aligned.m8n8.x4.shared.b16 {%0,%1,%2,%3}, [%4];"
                 : "=r"(r[0]), "=r"(r[1]), "=r"(r[2]), "=r"(r[3]) : "r"(addr));
}
__device__ __forceinline__ void mma16816(float* c, const uint32_t* a,
                                         uint32_t b0, uint32_t b1) {
    asm volatile(
        "mma.sync.aligned.m16n8k16.row.col.f32.f16.f16.f32 "
        "{%0,%1,%2,%3}, {%4,%5,%6,%7}, {%8,%9}, {%0,%1,%2,%3};"
        : "+f"(c[0]), "+f"(c[1]), "+f"(c[2]), "+f"(c[3])
        : "r"(a[0]), "r"(a[1]), "r"(a[2]), "r"(a[3]), "r"(b0), "r"(b1));
}

// ---------------------------------------------------------------------------
// Kernel 1: threefry spike generation, 8 pairs/thread, vectorized.
// Pair (i, i+HALFN): same column f, batches b and b+16. W1 2-part fp16 split
// on the first HID*FIN/8 threads.
// ---------------------------------------------------------------------------
__device__ __forceinline__ uint32_t rotl32(uint32_t x, int r) {
    return (x << r) | (x >> (32 - r));
}

__global__ void __launch_bounds__(256) spikegen_kernel(const float* __restrict__ inp,
                                                       const float* __restrict__ W1) {
    const uint32_t t = blockIdx.x * 256u + threadIdx.x;

    // --- W1 split, 8 consecutive elements per thread ---
    if (t < (HID * FIN) / 8) {
        int base = t * 8;
        int n = base / FIN, k = base % FIN;
        float4 wa = *(const float4*)&W1[base];
        float4 wb = *(const float4*)&W1[base + 4];
        float w[8] = {wa.x, wa.y, wa.z, wa.w, wb.x, wb.y, wb.z, wb.w};
        uint32_t hh[4], mm[4];
#pragma unroll
        for (int q = 0; q < 4; q++) {
            __half h0 = __float2half_rn(w[2 * q]);
            __half h1 = __float2half_rn(w[2 * q + 1]);
            __half m0 = __float2half_rn(w[2 * q] - __half2float(h0));
            __half m1 = __float2half_rn(w[2 * q + 1] - __half2float(h1));
            hh[q] = (uint32_t)__half_as_ushort(h0) | ((uint32_t)__half_as_ushort(h1) << 16);
            mm[q] = (uint32_t)__half_as_ushort(m0) | ((uint32_t)__half_as_ushort(m1) << 16);
        }
        *(uint4*)&g_W1s[(0 * NPAD + n) * FIN + k] = make_uint4(hh[0], hh[1], hh[2], hh[3]);
        *(uint4*)&g_W1s[(1 * NPAD + n) * FIN + k] = make_uint4(mm[0], mm[1], mm[2], mm[3]);
    }

    const uint32_t i0 = t * 8;
    if (i0 >= HALFN) return;

    const uint32_t ba = i0 / (TBINS * FIN);
    const uint32_t fa = i0 % FIN;                 // same f for both halves
    float4 p0 = *(const float4*)&inp[ba * FIN + fa];
    float4 p1 = *(const float4*)&inp[ba * FIN + fa + 4];
    float4 q0 = *(const float4*)&inp[(ba + 16) * FIN + fa];
    float4 q1 = *(const float4*)&inp[(ba + 16) * FIN + fa + 4];
    float pa[8] = {p0.x, p0.y, p0.z, p0.w, p1.x, p1.y, p1.z, p1.w};
    float pb[8] = {q0.x, q0.y, q0.z, q0.w, q1.x, q1.y, q1.z, q1.w};

    const uint32_t k0 = 0u, k1 = 42u, k2 = 0x1BD11BDAu ^ k0 ^ k1;
    unsigned short sa[8], sb[8];

#pragma unroll
    for (int j = 0; j < 8; j++) {
        uint32_t i = i0 + j;
        uint32_t x0 = i + k0;
        uint32_t x1 = (i + HALFN) + k1;
#define TF_RND(r) { x0 += x1; x1 = rotl32(x1, (r)) ^ x0; }
        TF_RND(13) TF_RND(15) TF_RND(26) TF_RND(6)
        x0 += k1; x1 += k2 + 1u;
        TF_RND(17) TF_RND(29) TF_RND(16) TF_RND(24)
        x0 += k2; x1 += k0 + 2u;
        TF_RND(13) TF_RND(15) TF_RND(26) TF_RND(6)
        x0 += k0; x1 += k1 + 3u;
        TF_RND(17) TF_RND(29) TF_RND(16) TF_RND(24)
        x0 += k1; x1 += k2 + 4u;
        TF_RND(13) TF_RND(15) TF_RND(26) TF_RND(6)
        x0 += k2; x1 += k0 + 5u;
#undef TF_RND
        float u0 = __uint_as_float((x0 >> 9) | 0x3F800000u) - 1.0f;
        float u1 = __uint_as_float((x1 >> 9) | 0x3F800000u) - 1.0f;
        sa[j] = (u0 < pa[j]) ? (unsigned short)0x3C00 : (unsigned short)0;
        sb[j] = (u1 < pb[j]) ? (unsigned short)0x3C00 : (unsigned short)0;
    }

    uint32_t oa[4], ob[4];
#pragma unroll
    for (int q = 0; q < 4; q++) {
        oa[q] = (uint32_t)sa[2 * q] | ((uint32_t)sa[2 * q + 1] << 16);
        ob[q] = (uint32_t)sb[2 * q] | ((uint32_t)sb[2 * q + 1] << 16);
    }
    *(uint4*)&g_spikes[i0]         = make_uint4(oa[0], oa[1], oa[2], oa[3]);
    *(uint4*)&g_spikes[i0 + HALFN] = make_uint4(ob[0], ob[1], ob[2], ob[3]);
}

// ---------------------------------------------------------------------------
// Kernel 2: GEMM1, mma.sync fp16, 4-stage cp.async pipeline, SW64 smem.
// a1[m,n] = sum_k spikes[m,k] * (W1hi + W1mid)[n,k]
// ---------------------------------------------------------------------------
__device__ __forceinline__ void load_stage(uint32_t sbase, int m0, int n0, int k0,
                                           int tid) {
    uint32_t stB = sbase + A_ST_BYTES;
#pragma unroll
    for (int c = tid; c < NCHUNK; c += 256) {
        uint32_t sa;
        const __half* g;
        if (c < ACHUNK) {
            int row = c >> 2, q = c & 3;
            int m = m0 + row;
            if (m >= MROWS) m = MROWS - 1;
            sa = sbase + SWZ64(row * 64 + q * 16);
            g = &g_spikes[(size_t)m * FIN + k0 + q * 8];
        } else {
            int cc = c - ACHUNK;
            int br = cc >> 2, q = cc & 3;
            int part = br >> 6, nr = br & 63;
            sa = stB + SWZ64(br * 64 + q * 16);
            g = &g_W1s[((size_t)part * NPAD + n0 + nr) * FIN + k0 + q * 8];
        }
        cp16(sa, g);
    }
    asm volatile("cp.async.commit_group;" ::: "memory");
}

__global__ void __launch_bounds__(256, 2) gemm1_mma_kernel() {
    extern __shared__ char dsmem[];
    const int tid = threadIdx.x;
    const int lane = tid & 31, wid = tid >> 5;
    const int wm = wid & 3;
    const int wn = wid >> 2;
    const int m0 = blockIdx.x * BM;
    const int n0 = blockIdx.y * BN;

    const uint32_t sbase = smem_u32(dsmem);

    float acc[4][4][4];
#pragma unroll
    for (int i = 0; i < 4; i++)
#pragma unroll
        for (int j = 0; j < 4; j++)
#pragma unroll
            for (int c = 0; c < 4; c++) acc[i][j][c] = 0.0f;

    const int ltr = (lane & 7) + ((lane >> 3) & 1) * 8;
    const int lkb = (lane >> 4) * 16;

    load_stage(sbase + 0 * STAGE_BYTES, m0, n0, 0 * BK, tid);
    load_stage(sbase + 1 * STAGE_BYTES, m0, n0, 1 * BK, tid);
    load_stage(sbase + 2 * STAGE_BYTES, m0, n0, 2 * BK, tid);

    for (int kc = 0; kc < KCH; kc++) {
        const int rem = KCH - 1 - kc;
        if (rem >= 2)      asm volatile("cp.async.wait_group 2;" ::: "memory");
        else if (rem == 1) asm volatile("cp.async.wait_group 1;" ::: "memory");
        else               asm volatile("cp.async.wait_group 0;" ::: "memory");
        __syncthreads();

        if (kc + 3 < KCH)
            load_stage(sbase + ((kc + 3) & 3) * STAGE_BYTES, m0, n0, (kc + 3) * BK, tid);

        const uint32_t sA = sbase + (kc & 3) * STAGE_BYTES;
        const uint32_t sB = sA + A_ST_BYTES;

#pragma unroll
        for (int kt = 0; kt < 2; kt++) {
            const int kb = kt * 32 + lkb;
            uint32_t aF[4][4];
#pragma unroll
            for (int im = 0; im < 4; im++) {
                int row = wm * 64 + im * 16 + ltr;
                ldsm4(aF[im], sA + SWZ64(row * 64 + kb));
            }
#pragma unroll
            for (int part = 0; part < NPARTS; part++) {
                uint32_t bF[2][4];
#pragma unroll
                for (int j = 0; j < 2; j++) {
                    int row = part * 64 + wn * 32 + j * 16 + ltr;
                    ldsm4(bF[j], sB + SWZ64(row * 64 + kb));
                }
#pragma unroll
                for (int im = 0; im < 4; im++)
#pragma unroll
                    for (int j = 0; j < 2; j++) {
                        mma16816(acc[im][j * 2 + 0], aF[im], bF[j][0], bF[j][2]);
                        mma16816(acc[im][j * 2 + 1], aF[im], bF[j][1], bF[j][3]);
                    }
            }
        }
    }

#pragma unroll
    for (int im = 0; im < 4; im++) {
        int m = m0 + wm * 64 + im * 16 + (lane >> 2);
#pragma unroll
        for (int jn = 0; jn < 4; jn++) {
            int n = n0 + wn * 32 + jn * 8 + (lane & 3) * 2;
            if (n < HID) {
                if (m < MROWS)
                    *(float2*)&g_a1[(size_t)m * HID + n] =
                        make_float2(acc[im][jn][0], acc[im][jn][1]);
                if (m + 8 < MROWS)
                    *(float2*)&g_a1[(size_t)(m + 8) * HID + n] =
                        make_float2(acc[im][jn][2], acc[im][jn][3]);
            }
        }
    }
}

// ---------------------------------------------------------------------------
// Kernel 3: PSP + threshold layer 1 -> bf16. Batch-10 prefetch.
// ---------------------------------------------------------------------------
__global__ void __launch_bounds__(256) psp1_kernel() {
    int tid = blockIdx.x * blockDim.x + threadIdx.x;
    if (tid >= BATCH * HID) return;
    int b = tid / HID;
    int o = tid % HID;
    const float* src = &g_a1[(size_t)b * TBINS * HID + o];
    __nv_bfloat16* dst = &g_s1[(size_t)b * TBINS * HID + o];
    float u = 0.0f;
    for (int tb = 0; tb < TBINS; tb += 10) {
        float x[10];
#pragma unroll
        for (int q = 0; q < 10; q++) x[q] = src[(tb + q) * HID];
#pragma unroll
        for (int q = 0; q < 10; q++) {
            u = fmaf(DECAY, u, x[q]);
            dst[(tb + q) * HID] = __float2bfloat16((u >= THETA) ? 1.0f : 0.0f);
        }
    }
}

// ---------------------------------------------------------------------------
// Kernel 4: GEMM2 (one warp per row, bf16x2 vectorized)
// ---------------------------------------------------------------------------
__global__ void __launch_bounds__(256) gemm2_kernel(const float* __restrict__ W2) {
    __shared__ float2 W2s[NOUT][(HID + 1) / 2 + 1];
    for (int idx = threadIdx.x; idx < NOUT * 206; idx += 256) {
        int j = idx / 206, kp = idx % 206;
        float w0 = (kp * 2 < HID) ? W2[j * HID + kp * 2] : 0.0f;
        float w1 = (kp * 2 + 1 < HID) ? W2[j * HID + kp * 2 + 1] : 0.0f;
        W2s[j][kp] = make_float2(w0, w1);
    }
    __syncthreads();

    int warp = threadIdx.x >> 5;
    int lane = threadIdx.x & 31;
    int m = blockIdx.x * 8 + warp;

    float p[NOUT];
#pragma unroll
    for (int j = 0; j < NOUT; j++) p[j] = 0.0f;

    for (int kp = lane; kp < 205; kp += 32) {
        __nv_bfloat162 sv = *(const __nv_bfloat162*)&g_s1[m * HID + kp * 2];
        float s0 = __bfloat162float(sv.x);
        float s1v = __bfloat162float(sv.y);
#pragma unroll
        for (int j = 0; j < NOUT; j++) {
            float2 w = W2s[j][kp];
            p[j] = fmaf(s0, w.x, fmaf(s1v, w.y, p[j]));
        }
    }

#pragma unroll
    for (int j = 0; j < NOUT; j++)
#pragma unroll
        for (int off = 16; off > 0; off >>= 1)
            p[j] += __shfl_down_sync(0xffffffffu, p[j], off);

    if (lane == 0) {
#pragma unroll
        for (int j = 0; j < NOUT; j++)
            g_a2[m * NOUT + j] = p[j];
    }
}

// ---------------------------------------------------------------------------
// Kernel 5: PSP + threshold layer 2 -> out[b, j, t]. Batch-10 prefetch.
// ---------------------------------------------------------------------------
__global__ void psp2_kernel(float* __restrict__ out) {
    int tid = blockIdx.x * blockDim.x + threadIdx.x;
    if (tid >= BATCH * NOUT) return;
    int b = tid / NOUT;
    int j = tid % NOUT;
    const float* src = &g_a2[(size_t)b * TBINS * NOUT + j];
    float* dst = &out[((size_t)b * NOUT + j) * TBINS];
    float u = 0.0f;
    for (int tb = 0; tb < TBINS; tb += 10) {
        float x[10];
#pragma unroll
        for (int q = 0; q < 10; q++) x[q] = src[(tb + q) * NOUT];
#pragma unroll
        for (int q = 0; q < 10; q++) {
            u = fmaf(DECAY, u, x[q]);
            dst[tb + q] = (u >= THETA) ? 1.0f : 0.0f;
        }
    }
}

// ---------------------------------------------------------------------------
extern "C" void kernel_launch(void* const* d_in, const int* in_sizes, int n_in,
                              void* d_out, int out_size) {
    const float* inp = (const float*)d_in[0];   // [32,3,32,32]
    const float* W1  = (const float*)d_in[1];   // [410,3072]
    const float* W2  = (const float*)d_in[2];   // [10,410]
    float* out = (float*)d_out;                 // [32,10,300]

    cudaFuncSetAttribute(gemm1_mma_kernel,
                         cudaFuncAttributeMaxDynamicSharedMemorySize, DSMEM_BYTES);

    spikegen_kernel<<<HALFN / 8 / 256, 256>>>(inp, W1);   // 7200 blocks

    dim3 g1((MROWS + BM - 1) / BM, NPAD / BN);   // (38, 7)
    gemm1_mma_kernel<<<g1, 256, DSMEM_BYTES>>>();

    psp1_kernel<<<(BATCH * HID + 255) / 256, 256>>>();
    gemm2_kernel<<<MROWS / 8, 256>>>(W2);
    psp2_kernel<<<2, 160>>>(out);
}

// round 13
// speedup vs baseline: 2.3737x; 1.5540x over previous
#include <cuda_runtime.h>
#include <cuda_fp16.h>
#include <cuda_bf16.h>
#include <cstdint>

// ===========================================================================
// SLAYER SNN forward. GEMM1: mma.sync.m16n8k16 fp16, 2-part fp16 split of W1
// (hi + mid), both fp32 accumulators (fastest mma.sync variant on sm_103:
// f16-acc same rate, s8 ~4x slower -- measured R8/R9).
// 4-stage cp.async pipeline (BK=32, SW64). Vectorized 8-pair threefry spikegen.
// R11 = identical re-bench of R10 (R10 run was clock-throttled: byte-identical
// gemm2 control kernel measured +42% vs R8/R9).
// ===========================================================================

#define BATCH 32
#define TBINS 300
#define FIN   3072
#define HID   410
#define NOUT  10
#define MROWS (BATCH * TBINS)          // 9600
#define NTOT  (MROWS * FIN)
#define HALFN (NTOT / 2)               // 14745600 = 4800*3072
#define NPAD  448

#define DECAY 0.90483743f
#define THETA 10.0f

// GEMM1 tiling
#define NPARTS 2
#define BM 256
#define BN 64
#define BK 32
#define KCH (FIN / BK)                 // 96
#define BROWS (NPARTS * BN)            // 128
#define A_ST_BYTES (BM * 64)           // 16384
#define B_ST_BYTES (BROWS * 64)        // 8192
#define STAGE_BYTES (A_ST_BYTES + B_ST_BYTES)   // 24576
#define NSTAGES 4
#define DSMEM_BYTES (NSTAGES * STAGE_BYTES)     // 98304
#define NCHUNK (STAGE_BYTES / 16)      // 1536
#define ACHUNK (A_ST_BYTES / 16)       // 1024

#define SWZ64(off) ((off) ^ (((off) >> 3) & 0x30))

// Scratch
__device__ __align__(16) __half        g_spikes[NTOT];
__device__ __align__(16) __half        g_W1s[NPARTS * NPAD * FIN];
__device__ __align__(16) float         g_a1[MROWS * HID];
__device__ __align__(16) __nv_bfloat16 g_s1[MROWS * HID];
__device__ __align__(16) float         g_a2[MROWS * NOUT];

// ---------------------------------------------------------------------------
__device__ __forceinline__ uint32_t smem_u32(const void* p) {
    uint32_t a;
    asm("{ .reg .u64 t; cvta.to.shared.u64 t, %1; cvt.u32.u64 %0, t; }" : "=r"(a) : "l"(p));
    return a;
}
__device__ __forceinline__ void cp16(uint32_t sa, const void* g) {
    asm volatile("cp.async.cg.shared.global [%0], [%1], 16;" :: "r"(sa), "l"(g));
}
__device__ __forceinline__ void ldsm4(uint32_t* r, uint32_t addr) {
    asm volatile("ldmatrix.sync.aligned.m8n8.x4.shared.b16 {%0,%1,%2,%3}, [%4];"
                 : "=r"(r[0]), "=r"(r[1]), "=r"(r[2]), "=r"(r[3]) : "r"(addr));
}
__device__ __forceinline__ void mma16816(float* c, const uint32_t* a,
                                         uint32_t b0, uint32_t b1) {
    asm volatile(
        "mma.sync.aligned.m16n8k16.row.col.f32.f16.f16.f32 "
        "{%0,%1,%2,%3}, {%4,%5,%6,%7}, {%8,%9}, {%0,%1,%2,%3};"
        : "+f"(c[0]), "+f"(c[1]), "+f"(c[2]), "+f"(c[3])
        : "r"(a[0]), "r"(a[1]), "r"(a[2]), "r"(a[3]), "r"(b0), "r"(b1));
}

// ---------------------------------------------------------------------------
// Kernel 1: threefry spike generation, 8 pairs/thread, vectorized.
// Pair (i, i+HALFN): same column f, batches b and b+16. W1 2-part fp16 split
// on the first HID*FIN/8 threads.
// ---------------------------------------------------------------------------
__device__ __forceinline__ uint32_t rotl32(uint32_t x, int r) {
    return (x << r) | (x >> (32 - r));
}

__global__ void __launch_bounds__(256) spikegen_kernel(const float* __restrict__ inp,
                                                       const float* __restrict__ W1) {
    const uint32_t t = blockIdx.x * 256u + threadIdx.x;

    // --- W1 split, 8 consecutive elements per thread ---
    if (t < (HID * FIN) / 8) {
        int base = t * 8;
        int n = base / FIN, k = base % FIN;
        float4 wa = *(const float4*)&W1[base];
        float4 wb = *(const float4*)&W1[base + 4];
        float w[8] = {wa.x, wa.y, wa.z, wa.w, wb.x, wb.y, wb.z, wb.w};
        uint32_t hh[4], mm[4];
#pragma unroll
        for (int q = 0; q < 4; q++) {
            __half h0 = __float2half_rn(w[2 * q]);
            __half h1 = __float2half_rn(w[2 * q + 1]);
            __half m0 = __float2half_rn(w[2 * q] - __half2float(h0));
            __half m1 = __float2half_rn(w[2 * q + 1] - __half2float(h1));
            hh[q] = (uint32_t)__half_as_ushort(h0) | ((uint32_t)__half_as_ushort(h1) << 16);
            mm[q] = (uint32_t)__half_as_ushort(m0) | ((uint32_t)__half_as_ushort(m1) << 16);
        }
        *(uint4*)&g_W1s[(0 * NPAD + n) * FIN + k] = make_uint4(hh[0], hh[1], hh[2], hh[3]);
        *(uint4*)&g_W1s[(1 * NPAD + n) * FIN + k] = make_uint4(mm[0], mm[1], mm[2], mm[3]);
    }

    const uint32_t i0 = t * 8;
    if (i0 >= HALFN) return;

    const uint32_t ba = i0 / (TBINS * FIN);
    const uint32_t fa = i0 % FIN;                 // same f for both halves
    float4 p0 = *(const float4*)&inp[ba * FIN + fa];
    float4 p1 = *(const float4*)&inp[ba * FIN + fa + 4];
    float4 q0 = *(const float4*)&inp[(ba + 16) * FIN + fa];
    float4 q1 = *(const float4*)&inp[(ba + 16) * FIN + fa + 4];
    float pa[8] = {p0.x, p0.y, p0.z, p0.w, p1.x, p1.y, p1.z, p1.w};
    float pb[8] = {q0.x, q0.y, q0.z, q0.w, q1.x, q1.y, q1.z, q1.w};

    const uint32_t k0 = 0u, k1 = 42u, k2 = 0x1BD11BDAu ^ k0 ^ k1;
    unsigned short sa[8], sb[8];

#pragma unroll
    for (int j = 0; j < 8; j++) {
        uint32_t i = i0 + j;
        uint32_t x0 = i + k0;
        uint32_t x1 = (i + HALFN) + k1;
#define TF_RND(r) { x0 += x1; x1 = rotl32(x1, (r)) ^ x0; }
        TF_RND(13) TF_RND(15) TF_RND(26) TF_RND(6)
        x0 += k1; x1 += k2 + 1u;
        TF_RND(17) TF_RND(29) TF_RND(16) TF_RND(24)
        x0 += k2; x1 += k0 + 2u;
        TF_RND(13) TF_RND(15) TF_RND(26) TF_RND(6)
        x0 += k0; x1 += k1 + 3u;
        TF_RND(17) TF_RND(29) TF_RND(16) TF_RND(24)
        x0 += k1; x1 += k2 + 4u;
        TF_RND(13) TF_RND(15) TF_RND(26) TF_RND(6)
        x0 += k2; x1 += k0 + 5u;
#undef TF_RND
        float u0 = __uint_as_float((x0 >> 9) | 0x3F800000u) - 1.0f;
        float u1 = __uint_as_float((x1 >> 9) | 0x3F800000u) - 1.0f;
        sa[j] = (u0 < pa[j]) ? (unsigned short)0x3C00 : (unsigned short)0;
        sb[j] = (u1 < pb[j]) ? (unsigned short)0x3C00 : (unsigned short)0;
    }

    uint32_t oa[4], ob[4];
#pragma unroll
    for (int q = 0; q < 4; q++) {
        oa[q] = (uint32_t)sa[2 * q] | ((uint32_t)sa[2 * q + 1] << 16);
        ob[q] = (uint32_t)sb[2 * q] | ((uint32_t)sb[2 * q + 1] << 16);
    }
    *(uint4*)&g_spikes[i0]         = make_uint4(oa[0], oa[1], oa[2], oa[3]);
    *(uint4*)&g_spikes[i0 + HALFN] = make_uint4(ob[0], ob[1], ob[2], ob[3]);
}

// ---------------------------------------------------------------------------
// Kernel 2: GEMM1, mma.sync fp16, 4-stage cp.async pipeline, SW64 smem.
// a1[m,n] = sum_k spikes[m,k] * (W1hi + W1mid)[n,k]
// ---------------------------------------------------------------------------
__device__ __forceinline__ void load_stage(uint32_t sbase, int m0, int n0, int k0,
                                           int tid) {
    uint32_t stB = sbase + A_ST_BYTES;
#pragma unroll
    for (int c = tid; c < NCHUNK; c += 256) {
        uint32_t sa;
        const __half* g;
        if (c < ACHUNK) {
            int row = c >> 2, q = c & 3;
            int m = m0 + row;
            if (m >= MROWS) m = MROWS - 1;
            sa = sbase + SWZ64(row * 64 + q * 16);
            g = &g_spikes[(size_t)m * FIN + k0 + q * 8];
        } else {
            int cc = c - ACHUNK;
            int br = cc >> 2, q = cc & 3;
            int part = br >> 6, nr = br & 63;
            sa = stB + SWZ64(br * 64 + q * 16);
            g = &g_W1s[((size_t)part * NPAD + n0 + nr) * FIN + k0 + q * 8];
        }
        cp16(sa, g);
    }
    asm volatile("cp.async.commit_group;" ::: "memory");
}

__global__ void __launch_bounds__(256, 2) gemm1_mma_kernel() {
    extern __shared__ char dsmem[];
    const int tid = threadIdx.x;
    const int lane = tid & 31, wid = tid >> 5;
    const int wm = wid & 3;
    const int wn = wid >> 2;
    const int m0 = blockIdx.x * BM;
    const int n0 = blockIdx.y * BN;

    const uint32_t sbase = smem_u32(dsmem);

    float acc[4][4][4];
#pragma unroll
    for (int i = 0; i < 4; i++)
#pragma unroll
        for (int j = 0; j < 4; j++)
#pragma unroll
            for (int c = 0; c < 4; c++) acc[i][j][c] = 0.0f;

    const int ltr = (lane & 7) + ((lane >> 3) & 1) * 8;
    const int lkb = (lane >> 4) * 16;

    load_stage(sbase + 0 * STAGE_BYTES, m0, n0, 0 * BK, tid);
    load_stage(sbase + 1 * STAGE_BYTES, m0, n0, 1 * BK, tid);
    load_stage(sbase + 2 * STAGE_BYTES, m0, n0, 2 * BK, tid);

    for (int kc = 0; kc < KCH; kc++) {
        const int rem = KCH - 1 - kc;
        if (rem >= 2)      asm volatile("cp.async.wait_group 2;" ::: "memory");
        else if (rem == 1) asm volatile("cp.async.wait_group 1;" ::: "memory");
        else               asm volatile("cp.async.wait_group 0;" ::: "memory");
        __syncthreads();

        if (kc + 3 < KCH)
            load_stage(sbase + ((kc + 3) & 3) * STAGE_BYTES, m0, n0, (kc + 3) * BK, tid);

        const uint32_t sA = sbase + (kc & 3) * STAGE_BYTES;
        const uint32_t sB = sA + A_ST_BYTES;

#pragma unroll
        for (int kt = 0; kt < 2; kt++) {
            const int kb = kt * 32 + lkb;
            uint32_t aF[4][4];
#pragma unroll
            for (int im = 0; im < 4; im++) {
                int row = wm * 64 + im * 16 + ltr;
                ldsm4(aF[im], sA + SWZ64(row * 64 + kb));
            }
#pragma unroll
            for (int part = 0; part < NPARTS; part++) {
                uint32_t bF[2][4];
#pragma unroll
                for (int j = 0; j < 2; j++) {
                    int row = part * 64 + wn * 32 + j * 16 + ltr;
                    ldsm4(bF[j], sB + SWZ64(row * 64 + kb));
                }
#pragma unroll
                for (int im = 0; im < 4; im++)
#pragma unroll
                    for (int j = 0; j < 2; j++) {
                        mma16816(acc[im][j * 2 + 0], aF[im], bF[j][0], bF[j][2]);
                        mma16816(acc[im][j * 2 + 1], aF[im], bF[j][1], bF[j][3]);
                    }
            }
        }
    }

#pragma unroll
    for (int im = 0; im < 4; im++) {
        int m = m0 + wm * 64 + im * 16 + (lane >> 2);
#pragma unroll
        for (int jn = 0; jn < 4; jn++) {
            int n = n0 + wn * 32 + jn * 8 + (lane & 3) * 2;
            if (n < HID) {
                if (m < MROWS)
                    *(float2*)&g_a1[(size_t)m * HID + n] =
                        make_float2(acc[im][jn][0], acc[im][jn][1]);
                if (m + 8 < MROWS)
                    *(float2*)&g_a1[(size_t)(m + 8) * HID + n] =
                        make_float2(acc[im][jn][2], acc[im][jn][3]);
            }
        }
    }
}

// ---------------------------------------------------------------------------
// Kernel 3: PSP + threshold layer 1 -> bf16. Batch-10 prefetch.
// ---------------------------------------------------------------------------
__global__ void __launch_bounds__(256) psp1_kernel() {
    int tid = blockIdx.x * blockDim.x + threadIdx.x;
    if (tid >= BATCH * HID) return;
    int b = tid / HID;
    int o = tid % HID;
    const float* src = &g_a1[(size_t)b * TBINS * HID + o];
    __nv_bfloat16* dst = &g_s1[(size_t)b * TBINS * HID + o];
    float u = 0.0f;
    for (int tb = 0; tb < TBINS; tb += 10) {
        float x[10];
#pragma unroll
        for (int q = 0; q < 10; q++) x[q] = src[(tb + q) * HID];
#pragma unroll
        for (int q = 0; q < 10; q++) {
            u = fmaf(DECAY, u, x[q]);
            dst[(tb + q) * HID] = __float2bfloat16((u >= THETA) ? 1.0f : 0.0f);
        }
    }
}

// ---------------------------------------------------------------------------
// Kernel 4: GEMM2 (one warp per row, bf16x2 vectorized)
// ---------------------------------------------------------------------------
__global__ void __launch_bounds__(256) gemm2_kernel(const float* __restrict__ W2) {
    __shared__ float2 W2s[NOUT][(HID + 1) / 2 + 1];
    for (int idx = threadIdx.x; idx < NOUT * 206; idx += 256) {
        int j = idx / 206, kp = idx % 206;
        float w0 = (kp * 2 < HID) ? W2[j * HID + kp * 2] : 0.0f;
        float w1 = (kp * 2 + 1 < HID) ? W2[j * HID + kp * 2 + 1] : 0.0f;
        W2s[j][kp] = make_float2(w0, w1);
    }
    __syncthreads();

    int warp = threadIdx.x >> 5;
    int lane = threadIdx.x & 31;
    int m = blockIdx.x * 8 + warp;

    float p[NOUT];
#pragma unroll
    for (int j = 0; j < NOUT; j++) p[j] = 0.0f;

    for (int kp = lane; kp < 205; kp += 32) {
        __nv_bfloat162 sv = *(const __nv_bfloat162*)&g_s1[m * HID + kp * 2];
        float s0 = __bfloat162float(sv.x);
        float s1v = __bfloat162float(sv.y);
#pragma unroll
        for (int j = 0; j < NOUT; j++) {
            float2 w = W2s[j][kp];
            p[j] = fmaf(s0, w.x, fmaf(s1v, w.y, p[j]));
        }
    }

#pragma unroll
    for (int j = 0; j < NOUT; j++)
#pragma unroll
        for (int off = 16; off > 0; off >>= 1)
            p[j] += __shfl_down_sync(0xffffffffu, p[j], off);

    if (lane == 0) {
#pragma unroll
        for (int j = 0; j < NOUT; j++)
            g_a2[m * NOUT + j] = p[j];
    }
}

// ---------------------------------------------------------------------------
// Kernel 5: PSP + threshold layer 2 -> out[b, j, t]. Batch-10 prefetch.
// ---------------------------------------------------------------------------
__global__ void psp2_kernel(float* __restrict__ out) {
    int tid = blockIdx.x * blockDim.x + threadIdx.x;
    if (tid >= BATCH * NOUT) return;
    int b = tid / NOUT;
    int j = tid % NOUT;
    const float* src = &g_a2[(size_t)b * TBINS * NOUT + j];
    float* dst = &out[((size_t)b * NOUT + j) * TBINS];
    float u = 0.0f;
    for (int tb = 0; tb < TBINS; tb += 10) {
        float x[10];
#pragma unroll
        for (int q = 0; q < 10; q++) x[q] = src[(tb + q) * NOUT];
#pragma unroll
        for (int q = 0; q < 10; q++) {
            u = fmaf(DECAY, u, x[q]);
            dst[tb + q] = (u >= THETA) ? 1.0f : 0.0f;
        }
    }
}

// ---------------------------------------------------------------------------
extern "C" void kernel_launch(void* const* d_in, const int* in_sizes, int n_in,
                              void* d_out, int out_size) {
    const float* inp = (const float*)d_in[0];   // [32,3,32,32]
    const float* W1  = (const float*)d_in[1];   // [410,3072]
    const float* W2  = (const float*)d_in[2];   // [10,410]
    float* out = (float*)d_out;                 // [32,10,300]

    cudaFuncSetAttribute(gemm1_mma_kernel,
                         cudaFuncAttributeMaxDynamicSharedMemorySize, DSMEM_BYTES);

    spikegen_kernel<<<HALFN / 8 / 256, 256>>>(inp, W1);   // 7200 blocks

    dim3 g1((MROWS + BM - 1) / BM, NPAD / BN);   // (38, 7)
    gemm1_mma_kernel<<<g1, 256, DSMEM_BYTES>>>();

    psp1_kernel<<<(BATCH * HID + 255) / 256, 256>>>();
    gemm2_kernel<<<MROWS / 8, 256>>>(W2);
    psp2_kernel<<<2, 160>>>(out);
}

// round 15
// speedup vs baseline: 2.4052x; 1.0132x over previous
#include <cuda_runtime.h>
#include <cuda_fp16.h>
#include <cstdint>

// ===========================================================================
// SLAYER SNN forward.
// GEMM1: mma.sync.m16n8k16 fp16 (fastest mma.sync on sm_103; f16-acc same
// rate, s8 4x slower -- measured R8/R9), 2-part fp16 split of W1, fp32 acc,
// BM=128 x BN=32 tiles (NPAD=416, -7% MMAs vs 448), 4-stage cp.async, SW64.
// GEMM2: packed fma.rn.f32x2 even/odd-k accumulators.
// Spikegen: vectorized 8-pair threefry (bit-exact vs jax).
// ===========================================================================

#define BATCH 32
#define TBINS 300
#define FIN   3072
#define HID   410
#define HID2  416                      // padded s1 row stride (16B-aligned rows)
#define NOUT  10
#define MROWS (BATCH * TBINS)          // 9600
#define NTOT  (MROWS * FIN)
#define HALFN (NTOT / 2)               // 14745600 = 4800*3072
#define NPAD  416                      // 13 tiles of 32

#define DECAY 0.90483743f
#define THETA 10.0f

// GEMM1 tiling
#define NPARTS 2
#define BM 128
#define BN 32
#define BK 32
#define KCH (FIN / BK)                 // 96
#define A_ST_BYTES (BM * 64)           // 8192
#define B_ST_BYTES (NPARTS * BN * 64)  // 4096
#define STAGE_BYTES (A_ST_BYTES + B_ST_BYTES)   // 12288
#define NSTAGES 4
#define DSMEM_BYTES (NSTAGES * STAGE_BYTES)     // 49152
#define NCHUNK (STAGE_BYTES / 16)      // 768
#define ACHUNK (A_ST_BYTES / 16)       // 512

#define SWZ64(off) ((off) ^ (((off) >> 3) & 0x30))

// Scratch
__device__ __align__(16) __half g_spikes[NTOT];
__device__ __align__(16) __half g_W1s[NPARTS * NPAD * FIN];  // rows >=410 stay 0
__device__ __align__(16) float  g_a1[MROWS * HID];
__device__ __align__(16) __half g_s1[MROWS * HID2];          // cols >=410 stay 0
__device__ __align__(16) float  g_a2[MROWS * NOUT];

// ---------------------------------------------------------------------------
__device__ __forceinline__ uint32_t smem_u32(const void* p) {
    uint32_t a;
    asm("{ .reg .u64 t; cvta.to.shared.u64 t, %1; cvt.u32.u64 %0, t; }" : "=r"(a) : "l"(p));
    return a;
}
__device__ __forceinline__ void cp16(uint32_t sa, const void* g) {
    asm volatile("cp.async.cg.shared.global [%0], [%1], 16;" :: "r"(sa), "l"(g));
}
__device__ __forceinline__ void ldsm4(uint32_t* r, uint32_t addr) {
    asm volatile("ldmatrix.sync.aligned.m8n8.x4.shared.b16 {%0,%1,%2,%3}, [%4];"
                 : "=r"(r[0]), "=r"(r[1]), "=r"(r[2]), "=r"(r[3]) : "r"(addr));
}
__device__ __forceinline__ void mma16816(float* c, const uint32_t* a,
                                         uint32_t b0, uint32_t b1) {
    asm volatile(
        "mma.sync.aligned.m16n8k16.row.col.f32.f16.f16.f32 "
        "{%0,%1,%2,%3}, {%4,%5,%6,%7}, {%8,%9}, {%0,%1,%2,%3};"
        : "+f"(c[0]), "+f"(c[1]), "+f"(c[2]), "+f"(c[3])
        : "r"(a[0]), "r"(a[1]), "r"(a[2]), "r"(a[3]), "r"(b0), "r"(b1));
}

// ---------------------------------------------------------------------------
// Kernel 1: threefry spike generation, 8 pairs/thread, vectorized.
// Pair (i, i+HALFN): same column f, batches b and b+16. W1 2-part fp16 split
// on the first HID*FIN/8 threads.
// ---------------------------------------------------------------------------
__device__ __forceinline__ uint32_t rotl32(uint32_t x, int r) {
    return (x << r) | (x >> (32 - r));
}

__global__ void __launch_bounds__(256) spikegen_kernel(const float* __restrict__ inp,
                                                       const float* __restrict__ W1) {
    const uint32_t t = blockIdx.x * 256u + threadIdx.x;

    // --- W1 split, 8 consecutive elements per thread ---
    if (t < (HID * FIN) / 8) {
        int base = t * 8;
        int n = base / FIN, k = base % FIN;
        float4 wa = *(const float4*)&W1[base];
        float4 wb = *(const float4*)&W1[base + 4];
        float w[8] = {wa.x, wa.y, wa.z, wa.w, wb.x, wb.y, wb.z, wb.w};
        uint32_t hh[4], mm[4];
#pragma unroll
        for (int q = 0; q < 4; q++) {
            __half h0 = __float2half_rn(w[2 * q]);
            __half h1 = __float2half_rn(w[2 * q + 1]);
            __half m0 = __float2half_rn(w[2 * q] - __half2float(h0));
            __half m1 = __float2half_rn(w[2 * q + 1] - __half2float(h1));
            hh[q] = (uint32_t)__half_as_ushort(h0) | ((uint32_t)__half_as_ushort(h1) << 16);
            mm[q] = (uint32_t)__half_as_ushort(m0) | ((uint32_t)__half_as_ushort(m1) << 16);
        }
        *(uint4*)&g_W1s[(0 * NPAD + n) * FIN + k] = make_uint4(hh[0], hh[1], hh[2], hh[3]);
        *(uint4*)&g_W1s[(1 * NPAD + n) * FIN + k] = make_uint4(mm[0], mm[1], mm[2], mm[3]);
    }

    const uint32_t i0 = t * 8;
    if (i0 >= HALFN) return;

    const uint32_t ba = i0 / (TBINS * FIN);
    const uint32_t fa = i0 % FIN;                 // same f for both halves
    float4 p0 = *(const float4*)&inp[ba * FIN + fa];
    float4 p1 = *(const float4*)&inp[ba * FIN + fa + 4];
    float4 q0 = *(const float4*)&inp[(ba + 16) * FIN + fa];
    float4 q1 = *(const float4*)&inp[(ba + 16) * FIN + fa + 4];
    float pa[8] = {p0.x, p0.y, p0.z, p0.w, p1.x, p1.y, p1.z, p1.w};
    float pb[8] = {q0.x, q0.y, q0.z, q0.w, q1.x, q1.y, q1.z, q1.w};

    const uint32_t k0 = 0u, k1 = 42u, k2 = 0x1BD11BDAu ^ k0 ^ k1;
    unsigned short sa[8], sb[8];

#pragma unroll
    for (int j = 0; j < 8; j++) {
        uint32_t i = i0 + j;
        uint32_t x0 = i + k0;
        uint32_t x1 = (i + HALFN) + k1;
#define TF_RND(r) { x0 += x1; x1 = rotl32(x1, (r)) ^ x0; }
        TF_RND(13) TF_RND(15) TF_RND(26) TF_RND(6)
        x0 += k1; x1 += k2 + 1u;
        TF_RND(17) TF_RND(29) TF_RND(16) TF_RND(24)
        x0 += k2; x1 += k0 + 2u;
        TF_RND(13) TF_RND(15) TF_RND(26) TF_RND(6)
        x0 += k0; x1 += k1 + 3u;
        TF_RND(17) TF_RND(29) TF_RND(16) TF_RND(24)
        x0 += k1; x1 += k2 + 4u;
        TF_RND(13) TF_RND(15) TF_RND(26) TF_RND(6)
        x0 += k2; x1 += k0 + 5u;
#undef TF_RND
        float u0 = __uint_as_float((x0 >> 9) | 0x3F800000u) - 1.0f;
        float u1 = __uint_as_float((x1 >> 9) | 0x3F800000u) - 1.0f;
        sa[j] = (u0 < pa[j]) ? (unsigned short)0x3C00 : (unsigned short)0;
        sb[j] = (u1 < pb[j]) ? (unsigned short)0x3C00 : (unsigned short)0;
    }

    uint32_t oa[4], ob[4];
#pragma unroll
    for (int q = 0; q < 4; q++) {
        oa[q] = (uint32_t)sa[2 * q] | ((uint32_t)sa[2 * q + 1] << 16);
        ob[q] = (uint32_t)sb[2 * q] | ((uint32_t)sb[2 * q + 1] << 16);
    }
    *(uint4*)&g_spikes[i0]         = make_uint4(oa[0], oa[1], oa[2], oa[3]);
    *(uint4*)&g_spikes[i0 + HALFN] = make_uint4(ob[0], ob[1], ob[2], ob[3]);
}

// ---------------------------------------------------------------------------
// Kernel 2: GEMM1, mma.sync fp16, BM=128 x BN=32, 4-stage cp.async, SW64.
// a1[m,n] = sum_k spikes[m,k] * (W1hi + W1mid)[n,k]
// ---------------------------------------------------------------------------
__device__ __forceinline__ void load_stage(uint32_t sbase, int m0, int n0, int k0,
                                           int tid) {
    uint32_t stB = sbase + A_ST_BYTES;
#pragma unroll
    for (int c = tid; c < NCHUNK; c += 256) {
        uint32_t sa;
        const __half* g;
        if (c < ACHUNK) {                           // A: 512 chunks (128 rows x 4)
            int row = c >> 2, q = c & 3;
            sa = sbase + SWZ64(row * 64 + q * 16);
            g = &g_spikes[(size_t)(m0 + row) * FIN + k0 + q * 8];
        } else {                                    // B: 256 chunks (64 rows x 4)
            int cc = c - ACHUNK;
            int br = cc >> 2, q = cc & 3;           // br 0..63
            int part = br >> 5, nr = br & 31;
            sa = stB + SWZ64(br * 64 + q * 16);
            g = &g_W1s[((size_t)part * NPAD + n0 + nr) * FIN + k0 + q * 8];
        }
        cp16(sa, g);
    }
    asm volatile("cp.async.commit_group;" ::: "memory");
}

__global__ void __launch_bounds__(256, 2) gemm1_mma_kernel() {
    extern __shared__ char dsmem[];
    const int tid = threadIdx.x;
    const int lane = tid & 31, wid = tid >> 5;
    const int wm = wid & 3;          // 4 m-warps (32 rows each)
    const int wn = wid >> 2;         // 2 n-warps (16 cols each)
    const int m0 = blockIdx.x * BM;
    const int n0 = blockIdx.y * BN;

    const uint32_t sbase = smem_u32(dsmem);

    float acc[2][2][4];
#pragma unroll
    for (int i = 0; i < 2; i++)
#pragma unroll
        for (int j = 0; j < 2; j++)
#pragma unroll
            for (int c = 0; c < 4; c++) acc[i][j][c] = 0.0f;

    const int ltr = (lane & 7) + ((lane >> 3) & 1) * 8;   // row within 16
    const int lkb = (lane >> 4) * 16;                     // 16B half select

    load_stage(sbase + 0 * STAGE_BYTES, m0, n0, 0 * BK, tid);
    load_stage(sbase + 1 * STAGE_BYTES, m0, n0, 1 * BK, tid);
    load_stage(sbase + 2 * STAGE_BYTES, m0, n0, 2 * BK, tid);

    for (int kc = 0; kc < KCH; kc++) {
        const int rem = KCH - 1 - kc;
        if (rem >= 2)      asm volatile("cp.async.wait_group 2;" ::: "memory");
        else if (rem == 1) asm volatile("cp.async.wait_group 1;" ::: "memory");
        else               asm volatile("cp.async.wait_group 0;" ::: "memory");
        __syncthreads();

        if (kc + 3 < KCH)
            load_stage(sbase + ((kc + 3) & 3) * STAGE_BYTES, m0, n0, (kc + 3) * BK, tid);

        const uint32_t sA = sbase + (kc & 3) * STAGE_BYTES;
        const uint32_t sB = sA + A_ST_BYTES;

#pragma unroll
        for (int kt = 0; kt < 2; kt++) {
            const int kb = kt * 32 + lkb;
            uint32_t aF[2][4];
#pragma unroll
            for (int im = 0; im < 2; im++) {
                int row = wm * 32 + im * 16 + ltr;
                ldsm4(aF[im], sA + SWZ64(row * 64 + kb));
            }
#pragma unroll
            for (int part = 0; part < NPARTS; part++) {
                uint32_t bF[4];
                {
                    int row = part * 32 + wn * 16 + ltr;
                    ldsm4(bF, sB + SWZ64(row * 64 + kb));
                }
#pragma unroll
                for (int im = 0; im < 2; im++)
#pragma unroll
                    for (int jn = 0; jn < 2; jn++)
                        mma16816(acc[im][jn], aF[im], bF[jn], bF[jn + 2]);
            }
        }
    }

#pragma unroll
    for (int im = 0; im < 2; im++) {
        int m = m0 + wm * 32 + im * 16 + (lane >> 2);
#pragma unroll
        for (int jn = 0; jn < 2; jn++) {
            int n = n0 + wn * 16 + jn * 8 + (lane & 3) * 2;
            if (n < HID) {
                *(float2*)&g_a1[(size_t)m * HID + n] =
                    make_float2(acc[im][jn][0], acc[im][jn][1]);
                *(float2*)&g_a1[(size_t)(m + 8) * HID + n] =
                    make_float2(acc[im][jn][2], acc[im][jn][3]);
            }
        }
    }
}

// ---------------------------------------------------------------------------
// Kernel 3: PSP + threshold layer 1 -> fp16 (stride HID2). Batch-10 prefetch.
// ---------------------------------------------------------------------------
__global__ void __launch_bounds__(256) psp1_kernel() {
    int tid = blockIdx.x * blockDim.x + threadIdx.x;
    if (tid >= BATCH * HID) return;
    int b = tid / HID;
    int o = tid % HID;
    const float* src = &g_a1[(size_t)b * TBINS * HID + o];
    __half* dst = &g_s1[(size_t)b * TBINS * HID2 + o];
    float u = 0.0f;
    for (int tb = 0; tb < TBINS; tb += 10) {
        float x[10];
#pragma unroll
        for (int q = 0; q < 10; q++) x[q] = src[(tb + q) * HID];
#pragma unroll
        for (int q = 0; q < 10; q++) {
            u = fmaf(DECAY, u, x[q]);
            dst[(tb + q) * HID2] =
                __ushort_as_half((u >= THETA) ? (unsigned short)0x3C00 : (unsigned short)0);
        }
    }
}

// ---------------------------------------------------------------------------
// Kernel 4: GEMM2 with packed fma.rn.f32x2 (even/odd-k partial sums packed).
// One warp per m-row; W2 pairs staged in smem, LDS.128 phase-conflict-free.
// ---------------------------------------------------------------------------
__global__ void __launch_bounds__(256) gemm2_kernel(const float* __restrict__ W2) {
    __shared__ __align__(16) float2 W2s[HID2 / 2][NOUT];   // [kp][j] = (W2[j][2kp], W2[j][2kp+1])
    for (int idx = threadIdx.x; idx < (HID2 / 2) * NOUT; idx += 256) {
        int kp = idx / NOUT, j = idx % NOUT;
        float w0 = (2 * kp < HID) ? W2[j * HID + 2 * kp] : 0.0f;
        float w1 = (2 * kp + 1 < HID) ? W2[j * HID + 2 * kp + 1] : 0.0f;
        W2s[kp][j] = make_float2(w0, w1);
    }
    __syncthreads();

    int warp = threadIdx.x >> 5;
    int lane = threadIdx.x & 31;
    int m = blockIdx.x * 8 + warp;

    unsigned long long p2[NOUT];
#pragma unroll
    for (int j = 0; j < NOUT; j++) p2[j] = 0ull;

    for (int kp = lane; kp < HID2 / 2; kp += 32) {
        __half2 hv = *(const __half2*)&g_s1[(size_t)m * HID2 + kp * 2];
        float2 sf = __half22float2(hv);
        unsigned long long s2;
        asm("mov.b64 %0, {%1, %2};" : "=l"(s2) : "f"(sf.x), "f"(sf.y));
#pragma unroll
        for (int jj = 0; jj < NOUT / 2; jj++) {
            ulonglong2 w = *(const ulonglong2*)&W2s[kp][jj * 2];
            asm("fma.rn.f32x2 %0, %1, %2, %0;" : "+l"(p2[jj * 2 + 0]) : "l"(s2), "l"(w.x));
            asm("fma.rn.f32x2 %0, %1, %2, %0;" : "+l"(p2[jj * 2 + 1]) : "l"(s2), "l"(w.y));
        }
    }

    float p[NOUT];
#pragma unroll
    for (int j = 0; j < NOUT; j++) {
        float lo, hi;
        asm("mov.b64 {%0, %1}, %2;" : "=f"(lo), "=f"(hi) : "l"(p2[j]));
        p[j] = lo + hi;
    }

#pragma unroll
    for (int j = 0; j < NOUT; j++)
#pragma unroll
        for (int off = 16; off > 0; off >>= 1)
            p[j] += __shfl_down_sync(0xffffffffu, p[j], off);

    if (lane == 0) {
#pragma unroll
        for (int j = 0; j < NOUT; j++)
            g_a2[m * NOUT + j] = p[j];
    }
}

// ---------------------------------------------------------------------------
// Kernel 5: PSP + threshold layer 2 -> out[b, j, t]. Batch-10 prefetch.
// ---------------------------------------------------------------------------
__global__ void psp2_kernel(float* __restrict__ out) {
    int tid = blockIdx.x * blockDim.x + threadIdx.x;
    if (tid >= BATCH * NOUT) return;
    int b = tid / NOUT;
    int j = tid % NOUT;
    const float* src = &g_a2[(size_t)b * TBINS * NOUT + j];
    float* dst = &out[((size_t)b * NOUT + j) * TBINS];
    float u = 0.0f;
    for (int tb = 0; tb < TBINS; tb += 10) {
        float x[10];
#pragma unroll
        for (int q = 0; q < 10; q++) x[q] = src[(tb + q) * NOUT];
#pragma unroll
        for (int q = 0; q < 10; q++) {
            u = fmaf(DECAY, u, x[q]);
            dst[tb + q] = (u >= THETA) ? 1.0f : 0.0f;
        }
    }
}

// ---------------------------------------------------------------------------
extern "C" void kernel_launch(void* const* d_in, const int* in_sizes, int n_in,
                              void* d_out, int out_size) {
    const float* inp = (const float*)d_in[0];   // [32,3,32,32]
    const float* W1  = (const float*)d_in[1];   // [410,3072]
    const float* W2  = (const float*)d_in[2];   // [10,410]
    float* out = (float*)d_out;                 // [32,10,300]

    cudaFuncSetAttribute(gemm1_mma_kernel,
                         cudaFuncAttributeMaxDynamicSharedMemorySize, DSMEM_BYTES);

    spikegen_kernel<<<HALFN / 8 / 256, 256>>>(inp, W1);   // 7200 blocks

    dim3 g1(MROWS / BM, NPAD / BN);   // (75, 13)
    gemm1_mma_kernel<<<g1, 256, DSMEM_BYTES>>>();

    psp1_kernel<<<(BATCH * HID + 255) / 256, 256>>>();
    gemm2_kernel<<<MROWS / 8, 256>>>(W2);
    psp2_kernel<<<2, 160>>>(out);
}